// round 1
// baseline (speedup 1.0000x reference)
#include <cuda_runtime.h>
#include <math.h>

#define B_    64
#define S_    80
#define H_    512
#define E_    512
#define T_    30
#define V_    32000
#define TS    29           // decode steps = T-1
#define M_ALL (TS * B_)    // 1856

// ---------------------------------------------------------------------------
// Scratch (static __device__ memory; no allocations anywhere)
// ---------------------------------------------------------------------------
struct Scratch {
    float w3v[H_];
    float w2v[H_];
    float wv[H_];
    float scores[B_ * S_];
    float context[B_ * H_];
    float gic[B_ * 3 * H_];
    float gh[B_ * 3 * H_];
    float h[B_ * H_];
    float embA[M_ALL * E_];        // gathered target embeddings, row r = t*64+b
    float gie[M_ALL * 3 * H_];     // embedding half of gi, all steps
    float hall[M_ALL * H_];        // h_new for every step, row r = t*64+b
};
__device__ Scratch g_s;

// ---------------------------------------------------------------------------
// out[c] = sum_r v[r] * M[r*ldm + c], c in [0,512)   (column-weighted matvec)
// ---------------------------------------------------------------------------
__global__ void colmatvec_k(const float* __restrict__ Mt, const float* __restrict__ v,
                            float* __restrict__ out, int ldm)
{
    __shared__ float sv[H_];
    int tid = threadIdx.x;                     // 512 threads
    sv[tid] = v[tid];
    __syncthreads();
    float acc = 0.f;
    #pragma unroll 4
    for (int r = 0; r < H_; r++)
        acc += sv[r] * Mt[(size_t)r * ldm + tid];
    out[tid] = acc;
}

// score[b,s] = enc[b,s,:] . wv       (one warp per row)
__global__ void scores_k(const float* __restrict__ enc, const float* __restrict__ wv,
                         float* __restrict__ scores)
{
    int row  = (blockIdx.x * blockDim.x + threadIdx.x) >> 5;
    int lane = threadIdx.x & 31;
    if (row >= B_ * S_) return;
    const float* e = enc + (size_t)row * H_;
    float acc = 0.f;
    #pragma unroll 4
    for (int k = lane; k < H_; k += 32) acc += e[k] * wv[k];
    #pragma unroll
    for (int o = 16; o; o >>= 1) acc += __shfl_xor_sync(0xffffffffu, acc, o);
    if (!lane) scores[row] = acc;
}

// softmax over s (per b) + context[b,f] = sum_s attn[b,s]*enc[b,s,f]
__global__ void softctx_k(const float* __restrict__ enc, const float* __restrict__ scores,
                          float* __restrict__ context)
{
    int b   = blockIdx.x;                     // 64 blocks, 256 threads
    int tid = threadIdx.x;
    __shared__ float at[S_];
    __shared__ float red[256];

    float sc = (tid < S_) ? scores[b * S_ + tid] : -1e30f;
    red[tid] = sc; __syncthreads();
    for (int s = 128; s; s >>= 1) { if (tid < s) red[tid] = fmaxf(red[tid], red[tid + s]); __syncthreads(); }
    float mx = red[0]; __syncthreads();

    float ex = (tid < S_) ? expf(sc - mx) : 0.f;
    red[tid] = ex; __syncthreads();
    for (int s = 128; s; s >>= 1) { if (tid < s) red[tid] += red[tid + s]; __syncthreads(); }
    float inv = 1.f / red[0];
    if (tid < S_) at[tid] = ex * inv;
    __syncthreads();

    const float* eb = enc + (size_t)b * S_ * H_;
    for (int f = tid; f < H_; f += 256) {
        float acc = 0.f;
        #pragma unroll 8
        for (int s = 0; s < S_; s++) acc += at[s] * eb[(size_t)s * H_ + f];
        context[b * H_ + f] = acc;
    }
}

// ---------------------------------------------------------------------------
// Small GEMM: C(64 x N) = A(64 x K) @ B(N x ldb, cols [boff,boff+K))^T + bias
// grid.x = N/32, 256 threads, thread tile 2x4
// ---------------------------------------------------------------------------
__global__ void gemm64_k(const float* __restrict__ A, const float* __restrict__ Bm,
                         const float* __restrict__ bias, float* __restrict__ C,
                         int N, int K, int ldb, int boff)
{
    const int BN = 32, BK = 16;
    __shared__ __align__(16) float As[BK][64];
    __shared__ __align__(16) float Bs[BK][BN];
    int tid  = threadIdx.x;
    int nblk = blockIdx.x * BN;
    int tx = tid & 7, tg = tid >> 3;          // n = tx*4, m = tg*2
    float acc[2][4] = {};

    for (int k0 = 0; k0 < K; k0 += BK) {
        {   // A: 64x16 = 256 float4, one per thread
            int m = tid >> 2, kk = (tid & 3) * 4;
            float4 av = *(const float4*)(A + (size_t)m * K + k0 + kk);
            As[kk + 0][m] = av.x; As[kk + 1][m] = av.y;
            As[kk + 2][m] = av.z; As[kk + 3][m] = av.w;
        }
        if (tid < 128) {  // B: 32x16 = 128 float4
            int n = tid >> 2, kk = (tid & 3) * 4;
            float4 bv = *(const float4*)(Bm + (size_t)(nblk + n) * ldb + boff + k0 + kk);
            Bs[kk + 0][n] = bv.x; Bs[kk + 1][n] = bv.y;
            Bs[kk + 2][n] = bv.z; Bs[kk + 3][n] = bv.w;
        }
        __syncthreads();
        #pragma unroll
        for (int kk = 0; kk < BK; kk++) {
            float a0 = As[kk][tg * 2 + 0], a1 = As[kk][tg * 2 + 1];
            float4 bv = *(const float4*)&Bs[kk][tx * 4];
            acc[0][0] += a0 * bv.x; acc[0][1] += a0 * bv.y; acc[0][2] += a0 * bv.z; acc[0][3] += a0 * bv.w;
            acc[1][0] += a1 * bv.x; acc[1][1] += a1 * bv.y; acc[1][2] += a1 * bv.z; acc[1][3] += a1 * bv.w;
        }
        __syncthreads();
    }
    #pragma unroll
    for (int i = 0; i < 2; i++) {
        int m = tg * 2 + i;
        #pragma unroll
        for (int j = 0; j < 4; j++) {
            int n = nblk + tx * 4 + j;
            C[(size_t)m * N + n] = acc[i][j] + (bias ? bias[n] : 0.f);
        }
    }
}

// ---------------------------------------------------------------------------
// Big GEMM: C(M x N) = A(M x K) @ B(N x ldb, cols [boff,boff+K))^T + bias
// 128x128x16 tiles, 256 threads, 8x8 register blocking
// mode 0: C row-major (r*N + n)
// mode 1: row r = t*64+b  ->  C[(b*TS + t)*N + n]   (logits layout (B,TS,V))
// ---------------------------------------------------------------------------
__global__ void gemm_big_k(const float* __restrict__ A, int M, int K,
                           const float* __restrict__ Bm, int ldb, int boff,
                           const float* __restrict__ bias,
                           float* __restrict__ C, int N, int mode)
{
    const int BM = 128, BN = 128, BK = 16;
    __shared__ __align__(16) float As[BK][BM];
    __shared__ __align__(16) float Bs[BK][BN];
    int tid = threadIdx.x;
    int m0 = blockIdx.y * BM, n0 = blockIdx.x * BN;
    int tx = tid & 15, ty = tid >> 4;        // n = tx*8, m = ty*8
    float acc[8][8] = {};

    for (int k0 = 0; k0 < K; k0 += BK) {
        #pragma unroll
        for (int i = 0; i < 2; i++) {        // A: 512 float4
            int q = tid + i * 256;
            int m = q >> 2, kk = (q & 3) * 4;
            float4 av = make_float4(0.f, 0.f, 0.f, 0.f);
            if (m0 + m < M) av = *(const float4*)(A + (size_t)(m0 + m) * K + k0 + kk);
            As[kk + 0][m] = av.x; As[kk + 1][m] = av.y;
            As[kk + 2][m] = av.z; As[kk + 3][m] = av.w;
        }
        #pragma unroll
        for (int i = 0; i < 2; i++) {        // B: 512 float4
            int q = tid + i * 256;
            int n = q >> 2, kk = (q & 3) * 4;
            float4 bv = *(const float4*)(Bm + (size_t)(n0 + n) * ldb + boff + k0 + kk);
            Bs[kk + 0][n] = bv.x; Bs[kk + 1][n] = bv.y;
            Bs[kk + 2][n] = bv.z; Bs[kk + 3][n] = bv.w;
        }
        __syncthreads();
        #pragma unroll
        for (int kk = 0; kk < BK; kk++) {
            float a[8], b[8];
            *(float4*)&a[0] = *(const float4*)&As[kk][ty * 8];
            *(float4*)&a[4] = *(const float4*)&As[kk][ty * 8 + 4];
            *(float4*)&b[0] = *(const float4*)&Bs[kk][tx * 8];
            *(float4*)&b[4] = *(const float4*)&Bs[kk][tx * 8 + 4];
            #pragma unroll
            for (int i = 0; i < 8; i++)
                #pragma unroll
                for (int j = 0; j < 8; j++)
                    acc[i][j] += a[i] * b[j];
        }
        __syncthreads();
    }
    #pragma unroll
    for (int i = 0; i < 8; i++) {
        int m = m0 + ty * 8 + i;
        if (m < M) {
            float* crow;
            if (mode == 0) crow = C + (size_t)m * N;
            else { int t = m >> 6, b = m & 63; crow = C + ((size_t)b * TS + t) * N; }
            #pragma unroll
            for (int j = 0; j < 8; j++) {
                int n = n0 + tx * 8 + j;
                crow[n] = acc[i][j] + (bias ? bias[n] : 0.f);
            }
        }
    }
}

// gather target embeddings: embA[(t*64+b)*512 + e] = embedding[targets[b,t], e]
__global__ void gather_k(const float* __restrict__ emb, const int* __restrict__ targets,
                         float* __restrict__ embA)
{
    int idx = blockIdx.x * blockDim.x + threadIdx.x;
    if (idx >= M_ALL * E_) return;
    int r = idx >> 9, e = idx & 511;
    int t = r >> 6, b = r & 63;
    int tok = targets[b * T_ + t];
    embA[idx] = emb[(size_t)tok * E_ + e];
}

__global__ void zero_k(float* __restrict__ p, int n)
{
    int i = blockIdx.x * blockDim.x + threadIdx.x;
    if (i < n) p[i] = 0.f;
}

// GRU gates: h_new = (1-z)*n + z*h ; also store into hall[t]
__global__ void gates_k(int t, const float* __restrict__ gie, const float* __restrict__ gic,
                        const float* __restrict__ gh, float* __restrict__ h,
                        float* __restrict__ hall)
{
    int idx = blockIdx.x * blockDim.x + threadIdx.x;   // 64*512
    if (idx >= B_ * H_) return;
    int b = idx >> 9, k = idx & 511;
    const float* ge = gie + ((size_t)t * B_ + b) * (3 * H_);
    const float* gc = gic + (size_t)b * (3 * H_);
    const float* gg = gh  + (size_t)b * (3 * H_);
    float r = 1.f / (1.f + expf(-(ge[k]          + gc[k]          + gg[k])));
    float z = 1.f / (1.f + expf(-(ge[H_ + k]     + gc[H_ + k]     + gg[H_ + k])));
    float n = tanhf(ge[2 * H_ + k] + gc[2 * H_ + k] + r * gg[2 * H_ + k]);
    float hp = h[idx];
    float hn = (1.f - z) * n + z * hp;
    h[idx] = hn;
    hall[((size_t)t * B_ + b) * H_ + k] = hn;
}

// argmax per (b,t) row of logits; preds written as float (output buffer dtype)
__global__ void argmax_k(const float* __restrict__ logits, float* __restrict__ preds)
{
    int q = blockIdx.x;                        // 0..1855 = b*29+t
    const float* row = logits + (size_t)q * V_;
    int tid = threadIdx.x;                     // 256
    float best = -3.4e38f; int bidx = 0x7fffffff;
    for (int v = tid; v < V_; v += 256) {
        float val = row[v];
        if (val > best) { best = val; bidx = v; }
    }
    __shared__ float sv[256]; __shared__ int si[256];
    sv[tid] = best; si[tid] = bidx; __syncthreads();
    for (int s = 128; s; s >>= 1) {
        if (tid < s) {
            if (sv[tid + s] > sv[tid] ||
                (sv[tid + s] == sv[tid] && si[tid + s] < si[tid])) {
                sv[tid] = sv[tid + s]; si[tid] = si[tid + s];
            }
        }
        __syncthreads();
    }
    if (!tid) preds[q] = (float)si[0];
}

// ---------------------------------------------------------------------------
extern "C" void kernel_launch(void* const* d_in, const int* in_sizes, int n_in,
                              void* d_out, int out_size)
{
    const float* enc     = (const float*)d_in[0];
    const int*   targets = (const int*)  d_in[1];
    const float* emb     = (const float*)d_in[2];
    const float* W1      = (const float*)d_in[3];
    // b1 (d_in[4]) drops out of softmax
    const float* W2      = (const float*)d_in[5];
    // b2 (d_in[6]) drops out
    const float* W3      = (const float*)d_in[7];
    // b3 (d_in[8]) drops out
    const float* v_att   = (const float*)d_in[9];
    const float* W_ih    = (const float*)d_in[10];
    const float* b_ih    = (const float*)d_in[11];
    const float* W_hh    = (const float*)d_in[12];
    const float* b_hh    = (const float*)d_in[13];
    const float* W_out   = (const float*)d_in[14];
    const float* b_out   = (const float*)d_in[15];
    float* out = (float*)d_out;

    Scratch* s;
    cudaGetSymbolAddress((void**)&s, g_s);

    // ---- attention is h-independent: collapse it entirely ----
    colmatvec_k<<<1, 512>>>(W3, v_att, s->w3v, H_);          // w3v = W3^T v_att
    colmatvec_k<<<1, 512>>>(W2, s->w3v, s->w2v, H_);         // w2v = W2^T w3v
    colmatvec_k<<<1, 512>>>(W1, s->w2v, s->wv, 2 * H_);      // wv  = W1_enc^T w2v
    scores_k<<<(B_ * S_ * 32 + 255) / 256, 256>>>(enc, s->wv, s->scores);
    softctx_k<<<B_, 256>>>(enc, s->scores, s->context);

    // gic = context @ W_ih[:,512:]^T + b_ih   (64 x 1536)
    gemm64_k<<<3 * H_ / 32, 256>>>(s->context, W_ih, b_ih, s->gic, 3 * H_, H_, H_ + E_, E_);

    // gie for all 29 steps: (1856 x 1536) = embA @ W_ih[:,:512]^T
    gather_k<<<(M_ALL * E_ + 255) / 256, 256>>>(emb, targets, s->embA);
    {
        dim3 grid(3 * H_ / 128, (M_ALL + 127) / 128);
        gemm_big_k<<<grid, 256>>>(s->embA, M_ALL, E_, W_ih, H_ + E_, 0, nullptr,
                                  s->gie, 3 * H_, 0);
    }

    // ---- sequential GRU recurrence (the only true critical path) ----
    zero_k<<<(B_ * H_ + 255) / 256, 256>>>(s->h, B_ * H_);
    for (int t = 0; t < TS; t++) {
        gemm64_k<<<3 * H_ / 32, 256>>>(s->h, W_hh, b_hh, s->gh, 3 * H_, H_, H_, 0);
        gates_k<<<(B_ * H_ + 255) / 256, 256>>>(t, s->gie, s->gic, s->gh, s->h, s->hall);
    }

    // ---- one batched logits GEMM: (1856 x 32000), K=512 ----
    {
        dim3 grid(V_ / 128, (M_ALL + 127) / 128);
        gemm_big_k<<<grid, 256>>>(s->hall, M_ALL, H_, W_out, H_, 0, b_out,
                                  out, V_, 1);
    }

    // ---- argmax predictions (if output buffer carries them) ----
    if (out_size >= (int)((size_t)M_ALL * V_ + M_ALL)) {
        argmax_k<<<M_ALL, 256>>>(out, out + (size_t)M_ALL * V_);
    }
}

// round 5
// speedup vs baseline: 1.6706x; 1.6706x over previous
#include <cuda_runtime.h>
#include <cuda_bf16.h>
#include <math.h>
#include <stdint.h>

#define B_    64
#define S_    80
#define H_    512
#define E_    512
#define T_    30
#define V_    32000
#define TS    29           // decode steps = T-1
#define M_ALL (TS * B_)    // 1856
#define M_PAD 1920         // 15 * 128

// ---------------------------------------------------------------------------
// Scratch (static __device__ memory; no allocations anywhere)
// ---------------------------------------------------------------------------
struct Scratch {
    float w3v[H_];
    float w2v[H_];
    float wv[H_];
    float scores[B_ * S_];
    float context[B_ * H_];
    float gic[B_ * 3 * H_];
    float gh[B_ * 3 * H_];
    float h[B_ * H_];
    float gie[M_ALL * 3 * H_];               // embedding half of gi, all steps
    __nv_bfloat16 emb_hi[M_PAD * E_];        // gathered embeddings, bf16 split
    __nv_bfloat16 emb_lo[M_PAD * E_];
    __nv_bfloat16 hall_hi[M_PAD * H_];       // h_new all steps, bf16 split
    __nv_bfloat16 hall_lo[M_PAD * H_];
    __nv_bfloat16 wih_hi[3 * H_ * H_];       // W_ih[:, :512] split
    __nv_bfloat16 wih_lo[3 * H_ * H_];
    __nv_bfloat16 wout_hi[(size_t)V_ * H_];  // W_out split
    __nv_bfloat16 wout_lo[(size_t)V_ * H_];
};
__device__ Scratch g_s;

__device__ __forceinline__ uint32_t smem_u32(const void* p) {
    uint32_t a;
    asm("{ .reg .u64 t; cvta.to.shared.u64 t, %1; cvt.u32.u64 %0, t; }" : "=r"(a) : "l"(p));
    return a;
}
__device__ __forceinline__ void cp_async16(uint32_t dst, const void* src) {
    asm volatile("cp.async.cg.shared.global [%0], [%1], 16;" :: "r"(dst), "l"(src));
}
__device__ __forceinline__ void ldsm_x4(uint32_t* r, uint32_t addr) {
    asm volatile("ldmatrix.sync.aligned.m8n8.x4.shared.b16 {%0,%1,%2,%3}, [%4];"
                 : "=r"(r[0]), "=r"(r[1]), "=r"(r[2]), "=r"(r[3]) : "r"(addr));
}
__device__ __forceinline__ void mma_bf16(float* d, const uint32_t* a, const uint32_t* b) {
    asm volatile("mma.sync.aligned.m16n8k16.row.col.f32.bf16.bf16.f32 "
                 "{%0,%1,%2,%3}, {%4,%5,%6,%7}, {%8,%9}, {%0,%1,%2,%3};"
                 : "+f"(d[0]), "+f"(d[1]), "+f"(d[2]), "+f"(d[3])
                 : "r"(a[0]), "r"(a[1]), "r"(a[2]), "r"(a[3]), "r"(b[0]), "r"(b[1]));
}

// ===========================================================================
// mma.sync GEMM: C(M x N) = A(M x 512) @ B(N x 512)^T + bias, bf16 split:
//   C = Ahi*Bhi + Ahi*Blo + Alo*Bhi   (fp32 accumulate)
// CTA tile 128x128, 256 threads (8 warps, warp tile 64x32), K chunks of 64,
// cp.async double-buffered, SW128-swizzled smem, ldmatrix fragments.
// mode 0: row-major C.  mode 1: row m=t*64+b -> C[(b*TS+t)*N + n]
// ===========================================================================
#define STG_BYTES 65536          // one stage: Ah 16K | Al 16K | Bh 16K | Bl 16K
#define MMA_SMEM  (2 * STG_BYTES)

__global__ void __launch_bounds__(256, 1) gemm_mma_k(
    const __nv_bfloat16* __restrict__ Ahi, const __nv_bfloat16* __restrict__ Alo,
    const __nv_bfloat16* __restrict__ Bhi, const __nv_bfloat16* __restrict__ Blo,
    const float* __restrict__ bias, float* __restrict__ C,
    int N, int Mv, int mode)
{
    extern __shared__ __align__(1024) char dsm[];
    const uint32_t sbase = smem_u32(dsm);
    const int tid = threadIdx.x, lane = tid & 31, wid = tid >> 5;
    const int warp_m = wid >> 2, warp_n = wid & 3;      // 2 x 4 warp grid
    const int m0 = blockIdx.y * 128, n0 = blockIdx.x * 128;

    float acc[4][4][4];
    #pragma unroll
    for (int i = 0; i < 4; i++)
        #pragma unroll
        for (int j = 0; j < 4; j++)
            #pragma unroll
            for (int r = 0; r < 4; r++) acc[i][j][r] = 0.f;

    // ---- stage loader: 4 tensors x 128 rows x 64 bf16 (128B swizzled rows) ----
    auto issue = [&](int c) {
        const int s = c & 1;
        const int kc = c * 64;
        #pragma unroll
        for (int j = 0; j < 16; j++) {
            const int t = j >> 2;
            const int idx2 = ((j & 3) << 8) + tid;
            const int row = idx2 >> 3, u = idx2 & 7;
            const __nv_bfloat16* src;
            int rb;
            if      (t == 0) { src = Ahi; rb = m0; }
            else if (t == 1) { src = Alo; rb = m0; }
            else if (t == 2) { src = Bhi; rb = n0; }
            else             { src = Blo; rb = n0; }
            const void* g = src + (size_t)(rb + row) * 512 + kc + u * 8;
            uint32_t d = sbase + s * STG_BYTES + t * 16384 + row * 128
                       + (((uint32_t)u ^ (uint32_t)(row & 7)) << 4);
            cp_async16(d, g);
        }
    };

    issue(0);
    asm volatile("cp.async.commit_group;" ::: "memory");

    for (int c = 0; c < 8; c++) {
        if (c + 1 < 8) {
            issue(c + 1);
            asm volatile("cp.async.commit_group;" ::: "memory");
            asm volatile("cp.async.wait_group 1;" ::: "memory");
        } else {
            asm volatile("cp.async.wait_group 0;" ::: "memory");
        }
        __syncthreads();

        const uint32_t stg = sbase + (c & 1) * STG_BYTES;
        #pragma unroll
        for (int ks = 0; ks < 4; ks++) {
            uint32_t ah[4][4], al[4][4];
            #pragma unroll
            for (int mi = 0; mi < 4; mi++) {
                int row = warp_m * 64 + mi * 16 + (lane & 15);
                uint32_t unit = ((uint32_t)(ks * 2 + (lane >> 4))) ^ (uint32_t)(row & 7);
                uint32_t a = stg + row * 128 + unit * 16;
                ldsm_x4(ah[mi], a);
                ldsm_x4(al[mi], a + 16384);
            }
            uint32_t bh[4][2], bl[4][2];
            #pragma unroll
            for (int p = 0; p < 2; p++) {
                int g = lane >> 3;
                int row = warp_n * 32 + (2 * p + (g >> 1)) * 8 + (lane & 7);
                uint32_t unit = ((uint32_t)(ks * 2 + (g & 1))) ^ (uint32_t)(row & 7);
                uint32_t a = stg + 32768 + row * 128 + unit * 16;
                uint32_t rh[4], rl[4];
                ldsm_x4(rh, a);
                ldsm_x4(rl, a + 16384);
                bh[2*p][0] = rh[0]; bh[2*p][1] = rh[1]; bh[2*p+1][0] = rh[2]; bh[2*p+1][1] = rh[3];
                bl[2*p][0] = rl[0]; bl[2*p][1] = rl[1]; bl[2*p+1][0] = rl[2]; bl[2*p+1][1] = rl[3];
            }
            #pragma unroll
            for (int mi = 0; mi < 4; mi++)
                #pragma unroll
                for (int ni = 0; ni < 4; ni++) {
                    mma_bf16(acc[mi][ni], ah[mi], bh[ni]);
                    mma_bf16(acc[mi][ni], ah[mi], bl[ni]);
                    mma_bf16(acc[mi][ni], al[mi], bh[ni]);
                }
        }
        __syncthreads();
    }

    // ---- epilogue ----
    #pragma unroll
    for (int mi = 0; mi < 4; mi++) {
        #pragma unroll
        for (int half = 0; half < 2; half++) {
            int m = m0 + warp_m * 64 + mi * 16 + (lane >> 2) + half * 8;
            if (m >= Mv) continue;
            float* crow;
            if (mode == 0) crow = C + (size_t)m * N;
            else { int t = m >> 6, b = m & 63; crow = C + ((size_t)b * TS + t) * N; }
            #pragma unroll
            for (int ni = 0; ni < 4; ni++) {
                int n = n0 + warp_n * 32 + ni * 8 + (lane & 3) * 2;
                float v0 = acc[mi][ni][half * 2 + 0];
                float v1 = acc[mi][ni][half * 2 + 1];
                if (bias) { v0 += bias[n]; v1 += bias[n + 1]; }
                float2 st = make_float2(v0, v1);
                *(float2*)&crow[n] = st;
            }
        }
    }
}

// ---------------------------------------------------------------------------
// bf16 hi/lo split kernels
// ---------------------------------------------------------------------------
__global__ void split_k(const float* __restrict__ src, __nv_bfloat16* __restrict__ hi,
                        __nv_bfloat16* __restrict__ lo, size_t n)
{
    size_t i = (size_t)blockIdx.x * blockDim.x + threadIdx.x;
    size_t stride = (size_t)gridDim.x * blockDim.x;
    for (; i < n; i += stride) {
        float v = src[i];
        __nv_bfloat16 h = __float2bfloat16(v);
        hi[i] = h;
        lo[i] = __float2bfloat16(v - __bfloat162float(h));
    }
}
__global__ void split_wih_k(const float* __restrict__ wih, __nv_bfloat16* __restrict__ hi,
                            __nv_bfloat16* __restrict__ lo)
{
    int i = blockIdx.x * blockDim.x + threadIdx.x;
    if (i >= 3 * H_ * H_) return;
    int n = i >> 9, k = i & 511;
    float v = wih[(size_t)n * (H_ + E_) + k];
    __nv_bfloat16 h = __float2bfloat16(v);
    hi[i] = h;
    lo[i] = __float2bfloat16(v - __bfloat162float(h));
}
__global__ void gather_split_k(const float* __restrict__ emb, const int* __restrict__ targets,
                               __nv_bfloat16* __restrict__ hi, __nv_bfloat16* __restrict__ lo)
{
    int idx = blockIdx.x * blockDim.x + threadIdx.x;
    if (idx >= M_PAD * E_) return;
    int r = idx >> 9, e = idx & 511;
    float v = 0.f;
    if (r < M_ALL) {
        int t = r >> 6, b = r & 63;
        v = emb[(size_t)targets[b * T_ + t] * E_ + e];
    }
    __nv_bfloat16 h = __float2bfloat16(v);
    hi[idx] = h;
    lo[idx] = __float2bfloat16(v - __bfloat162float(h));
}
__global__ void zero_pad_hall_k(__nv_bfloat16* __restrict__ hi, __nv_bfloat16* __restrict__ lo)
{
    int i = blockIdx.x * blockDim.x + threadIdx.x;
    int n = (M_PAD - M_ALL) * H_;
    if (i < n) { hi[M_ALL * H_ + i] = __float2bfloat16(0.f); lo[M_ALL * H_ + i] = __float2bfloat16(0.f); }
}

// ---------------------------------------------------------------------------
// attention collapse (h-independent): wv = W1_enc^T W2^T W3^T v_att
// ---------------------------------------------------------------------------
__global__ void colmatvec_k(const float* __restrict__ Mt, const float* __restrict__ v,
                            float* __restrict__ out, int ldm)
{
    __shared__ float sv[H_];
    int tid = threadIdx.x;
    sv[tid] = v[tid];
    __syncthreads();
    float acc = 0.f;
    #pragma unroll 4
    for (int r = 0; r < H_; r++) acc += sv[r] * Mt[(size_t)r * ldm + tid];
    out[tid] = acc;
}

__global__ void scores_k(const float* __restrict__ enc, const float* __restrict__ wv,
                         float* __restrict__ scores)
{
    int row  = (blockIdx.x * blockDim.x + threadIdx.x) >> 5;
    int lane = threadIdx.x & 31;
    if (row >= B_ * S_) return;
    const float* e = enc + (size_t)row * H_;
    float acc = 0.f;
    #pragma unroll 4
    for (int k = lane; k < H_; k += 32) acc += e[k] * wv[k];
    #pragma unroll
    for (int o = 16; o; o >>= 1) acc += __shfl_xor_sync(0xffffffffu, acc, o);
    if (!lane) scores[row] = acc;
}

__global__ void softctx_k(const float* __restrict__ enc, const float* __restrict__ scores,
                          float* __restrict__ context)
{
    int b = blockIdx.x, tid = threadIdx.x;
    __shared__ float at[S_];
    __shared__ float red[256];
    float sc = (tid < S_) ? scores[b * S_ + tid] : -1e30f;
    red[tid] = sc; __syncthreads();
    for (int s = 128; s; s >>= 1) { if (tid < s) red[tid] = fmaxf(red[tid], red[tid + s]); __syncthreads(); }
    float mx = red[0]; __syncthreads();
    float ex = (tid < S_) ? expf(sc - mx) : 0.f;
    red[tid] = ex; __syncthreads();
    for (int s = 128; s; s >>= 1) { if (tid < s) red[tid] += red[tid + s]; __syncthreads(); }
    float inv = 1.f / red[0];
    if (tid < S_) at[tid] = ex * inv;
    __syncthreads();
    const float* eb = enc + (size_t)b * S_ * H_;
    for (int f = tid; f < H_; f += 256) {
        float acc = 0.f;
        #pragma unroll 8
        for (int s = 0; s < S_; s++) acc += at[s] * eb[(size_t)s * H_ + f];
        context[b * H_ + f] = acc;
    }
}

// ---------------------------------------------------------------------------
// small GEMM: C(64 x N) = A(64 x K) @ B(N x ldb, cols [boff,boff+K))^T + bias
// ---------------------------------------------------------------------------
__global__ void gemm64_k(const float* __restrict__ A, const float* __restrict__ Bm,
                         const float* __restrict__ bias, float* __restrict__ C,
                         int N, int K, int ldb, int boff)
{
    const int BN = 32, BK = 16;
    __shared__ __align__(16) float As[BK][64];
    __shared__ __align__(16) float Bs[BK][BN];
    int tid = threadIdx.x;
    int nblk = blockIdx.x * BN;
    int tx = tid & 7, tg = tid >> 3;
    float acc[2][4] = {};
    for (int k0 = 0; k0 < K; k0 += BK) {
        {
            int m = tid >> 2, kk = (tid & 3) * 4;
            float4 av = *(const float4*)(A + (size_t)m * K + k0 + kk);
            As[kk + 0][m] = av.x; As[kk + 1][m] = av.y;
            As[kk + 2][m] = av.z; As[kk + 3][m] = av.w;
        }
        if (tid < 128) {
            int n = tid >> 2, kk = (tid & 3) * 4;
            float4 bv = *(const float4*)(Bm + (size_t)(nblk + n) * ldb + boff + k0 + kk);
            Bs[kk + 0][n] = bv.x; Bs[kk + 1][n] = bv.y;
            Bs[kk + 2][n] = bv.z; Bs[kk + 3][n] = bv.w;
        }
        __syncthreads();
        #pragma unroll
        for (int kk = 0; kk < BK; kk++) {
            float a0 = As[kk][tg * 2 + 0], a1 = As[kk][tg * 2 + 1];
            float4 bv = *(const float4*)&Bs[kk][tx * 4];
            acc[0][0] += a0 * bv.x; acc[0][1] += a0 * bv.y; acc[0][2] += a0 * bv.z; acc[0][3] += a0 * bv.w;
            acc[1][0] += a1 * bv.x; acc[1][1] += a1 * bv.y; acc[1][2] += a1 * bv.z; acc[1][3] += a1 * bv.w;
        }
        __syncthreads();
    }
    #pragma unroll
    for (int i = 0; i < 2; i++) {
        int m = tg * 2 + i;
        #pragma unroll
        for (int j = 0; j < 4; j++) {
            int n = nblk + tx * 4 + j;
            C[(size_t)m * N + n] = acc[i][j] + (bias ? bias[n] : 0.f);
        }
    }
}

__global__ void zero_k(float* __restrict__ p, int n)
{
    int i = blockIdx.x * blockDim.x + threadIdx.x;
    if (i < n) p[i] = 0.f;
}

// GRU gates: h_new = (1-z)*n + z*h ; write fp32 h and bf16-split hall
__global__ void gates_k(int t, const float* __restrict__ gie, const float* __restrict__ gic,
                        const float* __restrict__ gh, float* __restrict__ h,
                        __nv_bfloat16* __restrict__ hallhi, __nv_bfloat16* __restrict__ halllo)
{
    int idx = blockIdx.x * blockDim.x + threadIdx.x;
    if (idx >= B_ * H_) return;
    int b = idx >> 9, k = idx & 511;
    const float* ge = gie + ((size_t)t * B_ + b) * (3 * H_);
    const float* gc = gic + (size_t)b * (3 * H_);
    const float* gg = gh  + (size_t)b * (3 * H_);
    float r = 1.f / (1.f + expf(-(ge[k]          + gc[k]          + gg[k])));
    float z = 1.f / (1.f + expf(-(ge[H_ + k]     + gc[H_ + k]     + gg[H_ + k])));
    float n = tanhf(ge[2 * H_ + k] + gc[2 * H_ + k] + r * gg[2 * H_ + k]);
    float hn = (1.f - z) * n + z * h[idx];
    h[idx] = hn;
    __nv_bfloat16 hh = __float2bfloat16(hn);
    size_t o = ((size_t)t * B_ + b) * H_ + k;
    hallhi[o] = hh;
    halllo[o] = __float2bfloat16(hn - __bfloat162float(hh));
}

__global__ void argmax_k(const float* __restrict__ logits, float* __restrict__ preds)
{
    int q = blockIdx.x;
    const float* row = logits + (size_t)q * V_;
    int tid = threadIdx.x;
    float best = -3.4e38f; int bidx = 0x7fffffff;
    for (int v = tid; v < V_; v += 256) {
        float val = row[v];
        if (val > best) { best = val; bidx = v; }
    }
    __shared__ float sv[256]; __shared__ int si[256];
    sv[tid] = best; si[tid] = bidx; __syncthreads();
    for (int s = 128; s; s >>= 1) {
        if (tid < s) {
            if (sv[tid + s] > sv[tid] ||
                (sv[tid + s] == sv[tid] && si[tid + s] < si[tid])) {
                sv[tid] = sv[tid + s]; si[tid] = si[tid + s];
            }
        }
        __syncthreads();
    }
    if (!tid) preds[q] = (float)si[0];
}

// ---------------------------------------------------------------------------
extern "C" void kernel_launch(void* const* d_in, const int* in_sizes, int n_in,
                              void* d_out, int out_size)
{
    const float* enc     = (const float*)d_in[0];
    const int*   targets = (const int*)  d_in[1];
    const float* emb     = (const float*)d_in[2];
    const float* W1      = (const float*)d_in[3];
    const float* W2      = (const float*)d_in[5];
    const float* W3      = (const float*)d_in[7];
    const float* v_att   = (const float*)d_in[9];
    const float* W_ih    = (const float*)d_in[10];
    const float* b_ih    = (const float*)d_in[11];
    const float* W_hh    = (const float*)d_in[12];
    const float* b_hh    = (const float*)d_in[13];
    const float* W_out   = (const float*)d_in[14];
    const float* b_out   = (const float*)d_in[15];
    float* out = (float*)d_out;

    Scratch* s;
    cudaGetSymbolAddress((void**)&s, g_s);
    cudaFuncSetAttribute(gemm_mma_k, cudaFuncAttributeMaxDynamicSharedMemorySize, MMA_SMEM);

    // ---- weight / activation splits ----
    split_k<<<4096, 256>>>(W_out, s->wout_hi, s->wout_lo, (size_t)V_ * H_);
    split_wih_k<<<(3 * H_ * H_ + 255) / 256, 256>>>(W_ih, s->wih_hi, s->wih_lo);
    gather_split_k<<<(M_PAD * E_ + 255) / 256, 256>>>(emb, targets, s->emb_hi, s->emb_lo);
    zero_pad_hall_k<<<((M_PAD - M_ALL) * H_ + 255) / 256, 256>>>(s->hall_hi, s->hall_lo);

    // ---- attention is h-independent: collapse it entirely ----
    colmatvec_k<<<1, 512>>>(W3, v_att, s->w3v, H_);
    colmatvec_k<<<1, 512>>>(W2, s->w3v, s->w2v, H_);
    colmatvec_k<<<1, 512>>>(W1, s->w2v, s->wv, 2 * H_);
    scores_k<<<(B_ * S_ * 32 + 255) / 256, 256>>>(enc, s->wv, s->scores);
    softctx_k<<<B_, 256>>>(enc, s->scores, s->context);

    // gic = context @ W_ih[:,512:]^T + b_ih   (64 x 1536)
    gemm64_k<<<3 * H_ / 32, 256>>>(s->context, W_ih, b_ih, s->gic, 3 * H_, H_, H_ + E_, E_);

    // gie (1856 x 1536) = embA @ W_ih[:, :512]^T — tensor-core split GEMM
    {
        dim3 grid(3 * H_ / 128, M_PAD / 128);
        gemm_mma_k<<<grid, 256, MMA_SMEM>>>(s->emb_hi, s->emb_lo, s->wih_hi, s->wih_lo,
                                            nullptr, s->gie, 3 * H_, M_ALL, 0);
    }

    // ---- sequential GRU recurrence ----
    zero_k<<<(B_ * H_ + 255) / 256, 256>>>(s->h, B_ * H_);
    for (int t = 0; t < TS; t++) {
        gemm64_k<<<3 * H_ / 32, 256>>>(s->h, W_hh, b_hh, s->gh, 3 * H_, H_, H_, 0);
        gates_k<<<(B_ * H_ + 255) / 256, 256>>>(t, s->gie, s->gic, s->gh, s->h,
                                                s->hall_hi, s->hall_lo);
    }

    // ---- logits (1856 x 32000) = hall @ W_out^T + b_out — tensor-core split GEMM ----
    {
        dim3 grid(V_ / 128, M_PAD / 128);
        gemm_mma_k<<<grid, 256, MMA_SMEM>>>(s->hall_hi, s->hall_lo, s->wout_hi, s->wout_lo,
                                            b_out, out, V_, M_ALL, 1);
    }

    // ---- argmax predictions ----
    if (out_size >= (int)((size_t)M_ALL * V_ + M_ALL)) {
        argmax_k<<<M_ALL, 256>>>(out, out + (size_t)M_ALL * V_);
    }
}

// round 7
// speedup vs baseline: 2.2392x; 1.3404x over previous
#include <cuda_runtime.h>
#include <cuda_bf16.h>
#include <math.h>
#include <stdint.h>

#define B_    64
#define S_    80
#define H_    512
#define E_    512
#define T_    30
#define V_    32000
#define TS    29           // decode steps = T-1
#define M_ALL (TS * B_)    // 1856
#define M_PAD 1920         // 15 * 128

// ---------------------------------------------------------------------------
// Scratch (static __device__ memory; no allocations anywhere)
// ---------------------------------------------------------------------------
struct Scratch {
    float w3v[H_];
    float w2v[H_];
    float wv[H_];
    float scores[B_ * S_];
    float context[B_ * H_];
    float gic[B_ * 3 * H_];
    float gh_part[4 * B_ * 3 * H_];          // split-K partials of h @ W_hh^T
    float h[B_ * H_];
    float gie[M_ALL * 3 * H_];               // embedding half of gi, all steps
    unsigned long long amax[M_ALL];          // fused argmax keys
    __nv_bfloat16 emb_hi[M_PAD * E_];        // gathered embeddings, bf16 split
    __nv_bfloat16 emb_lo[M_PAD * E_];
    __nv_bfloat16 hall_hi[M_PAD * H_];       // h_new all steps, bf16 split
    __nv_bfloat16 hall_lo[M_PAD * H_];
    __nv_bfloat16 wih_hi[3 * H_ * H_];       // W_ih[:, :512] split
    __nv_bfloat16 wih_lo[3 * H_ * H_];
    __nv_bfloat16 wout_hi[(size_t)V_ * H_];  // W_out split
    __nv_bfloat16 wout_lo[(size_t)V_ * H_];
};
__device__ Scratch g_s;

__device__ __forceinline__ uint32_t smem_u32(const void* p) {
    uint32_t a;
    asm("{ .reg .u64 t; cvta.to.shared.u64 t, %1; cvt.u32.u64 %0, t; }" : "=r"(a) : "l"(p));
    return a;
}
__device__ __forceinline__ void cp_async16(uint32_t dst, const void* src) {
    asm volatile("cp.async.cg.shared.global [%0], [%1], 16;" :: "r"(dst), "l"(src));
}
__device__ __forceinline__ void ldsm_x4(uint32_t* r, uint32_t addr) {
    asm volatile("ldmatrix.sync.aligned.m8n8.x4.shared.b16 {%0,%1,%2,%3}, [%4];"
                 : "=r"(r[0]), "=r"(r[1]), "=r"(r[2]), "=r"(r[3]) : "r"(addr));
}
__device__ __forceinline__ void mma_bf16(float* d, const uint32_t* a, const uint32_t* b) {
    asm volatile("mma.sync.aligned.m16n8k16.row.col.f32.bf16.bf16.f32 "
                 "{%0,%1,%2,%3}, {%4,%5,%6,%7}, {%8,%9}, {%0,%1,%2,%3};"
                 : "+f"(d[0]), "+f"(d[1]), "+f"(d[2]), "+f"(d[3])
                 : "r"(a[0]), "r"(a[1]), "r"(a[2]), "r"(a[3]), "r"(b[0]), "r"(b[1]));
}
// monotonic float -> uint order map
__device__ __forceinline__ uint32_t ford(float f) {
    uint32_t u = __float_as_uint(f);
    return u ^ ((uint32_t)((int32_t)u >> 31) | 0x80000000u);
}

// ===========================================================================
// mma.sync GEMM: C(M x N) = A(M x 512) @ B(N x 512)^T + bias, bf16 split:
//   C = Ahi*Bhi + Ahi*Blo + Alo*Bhi   (fp32 accumulate)
// CTA tile 128x128, 256 threads (8 warps, warp tile 64x32), K chunks of 64,
// cp.async 3-stage pipeline, SW128-swizzled smem, ldmatrix fragments.
// mode 0: row-major C.  mode 1: row m=t*64+b -> C[(b*TS+t)*N + n]
// amax (optional): per-global-row argmax keys merged via atomicMax.
// ===========================================================================
#define STG_BYTES 65536          // one stage: Ah 16K | Al 16K | Bh 16K | Bl 16K
#define MMA_SMEM  (3 * STG_BYTES)

__global__ void __launch_bounds__(256, 1) gemm_mma_k(
    const __nv_bfloat16* __restrict__ Ahi, const __nv_bfloat16* __restrict__ Alo,
    const __nv_bfloat16* __restrict__ Bhi, const __nv_bfloat16* __restrict__ Blo,
    const float* __restrict__ bias, float* __restrict__ C,
    int N, int Mv, int mode, unsigned long long* __restrict__ amax)
{
    extern __shared__ __align__(1024) char dsm[];
    const uint32_t sbase = smem_u32(dsm);
    const int tid = threadIdx.x, lane = tid & 31, wid = tid >> 5;
    const int warp_m = wid >> 2, warp_n = wid & 3;      // 2 x 4 warp grid
    const int m0 = blockIdx.y * 128, n0 = blockIdx.x * 128;

    float acc[4][4][4];
    #pragma unroll
    for (int i = 0; i < 4; i++)
        #pragma unroll
        for (int j = 0; j < 4; j++)
            #pragma unroll
            for (int r = 0; r < 4; r++) acc[i][j][r] = 0.f;

    // ---- stage loader: 4 tensors x 128 rows x 64 bf16 (128B swizzled rows) ----
    auto issue = [&](int c) {
        const int s = c % 3;
        const int kc = c * 64;
        #pragma unroll
        for (int j = 0; j < 16; j++) {
            const int t = j >> 2;
            const int idx2 = ((j & 3) << 8) + tid;
            const int row = idx2 >> 3, u = idx2 & 7;
            const __nv_bfloat16* src;
            int rb;
            if      (t == 0) { src = Ahi; rb = m0; }
            else if (t == 1) { src = Alo; rb = m0; }
            else if (t == 2) { src = Bhi; rb = n0; }
            else             { src = Blo; rb = n0; }
            const void* g = src + (size_t)(rb + row) * 512 + kc + u * 8;
            uint32_t d = sbase + s * STG_BYTES + t * 16384 + row * 128
                       + (((uint32_t)u ^ (uint32_t)(row & 7)) << 4);
            cp_async16(d, g);
        }
    };

    issue(0);
    asm volatile("cp.async.commit_group;" ::: "memory");
    issue(1);
    asm volatile("cp.async.commit_group;" ::: "memory");

    for (int c = 0; c < 8; c++) {
        if (c + 2 < 8) {
            issue(c + 2);
            asm volatile("cp.async.commit_group;" ::: "memory");
        }
        if (c <= 5)      asm volatile("cp.async.wait_group 2;" ::: "memory");
        else if (c == 6) asm volatile("cp.async.wait_group 1;" ::: "memory");
        else             asm volatile("cp.async.wait_group 0;" ::: "memory");
        __syncthreads();

        const uint32_t stg = sbase + (c % 3) * STG_BYTES;
        #pragma unroll
        for (int ks = 0; ks < 4; ks++) {
            uint32_t ah[4][4], al[4][4];
            #pragma unroll
            for (int mi = 0; mi < 4; mi++) {
                int row = warp_m * 64 + mi * 16 + (lane & 15);
                uint32_t unit = ((uint32_t)(ks * 2 + (lane >> 4))) ^ (uint32_t)(row & 7);
                uint32_t a = stg + row * 128 + unit * 16;
                ldsm_x4(ah[mi], a);
                ldsm_x4(al[mi], a + 16384);
            }
            uint32_t bh[4][2], bl[4][2];
            #pragma unroll
            for (int p = 0; p < 2; p++) {
                int g = lane >> 3;
                int row = warp_n * 32 + (2 * p + (g >> 1)) * 8 + (lane & 7);
                uint32_t unit = ((uint32_t)(ks * 2 + (g & 1))) ^ (uint32_t)(row & 7);
                uint32_t a = stg + 32768 + row * 128 + unit * 16;
                uint32_t rh[4], rl[4];
                ldsm_x4(rh, a);
                ldsm_x4(rl, a + 16384);
                bh[2*p][0] = rh[0]; bh[2*p][1] = rh[1]; bh[2*p+1][0] = rh[2]; bh[2*p+1][1] = rh[3];
                bl[2*p][0] = rl[0]; bl[2*p][1] = rl[1]; bl[2*p+1][0] = rl[2]; bl[2*p+1][1] = rl[3];
            }
            #pragma unroll
            for (int mi = 0; mi < 4; mi++)
                #pragma unroll
                for (int ni = 0; ni < 4; ni++) {
                    mma_bf16(acc[mi][ni], ah[mi], bh[ni]);
                    mma_bf16(acc[mi][ni], ah[mi], bl[ni]);
                    mma_bf16(acc[mi][ni], al[mi], bh[ni]);
                }
        }
        __syncthreads();
    }

    // ---- epilogue (+ optional fused per-row argmax) ----
    unsigned long long* skey = (unsigned long long*)dsm;   // reuse smem: [128][4]
    #pragma unroll
    for (int mi = 0; mi < 4; mi++) {
        #pragma unroll
        for (int half = 0; half < 2; half++) {
            int mloc = warp_m * 64 + mi * 16 + (lane >> 2) + half * 8;
            int m = m0 + mloc;
            bool live = (m < Mv);
            float* crow = C;
            int grow = 0;
            if (live) {
                if (mode == 0) crow = C + (size_t)m * N;
                else { int t = m >> 6, b = m & 63; grow = b * TS + t; crow = C + (size_t)grow * N; }
            }
            float bmax = -3.4e38f; int bidx = 0;
            #pragma unroll
            for (int ni = 0; ni < 4; ni++) {
                int n = n0 + warp_n * 32 + ni * 8 + (lane & 3) * 2;
                float v0 = acc[mi][ni][half * 2 + 0];
                float v1 = acc[mi][ni][half * 2 + 1];
                if (bias) { v0 += bias[n]; v1 += bias[n + 1]; }
                if (live) {
                    *(float2*)&crow[n] = make_float2(v0, v1);
                    if (amax) {
                        if (v0 > bmax) { bmax = v0; bidx = n; }
                        if (v1 > bmax) { bmax = v1; bidx = n + 1; }
                    }
                }
            }
            if (amax) {
                // reduce (max,firstidx) over the 4 lanes sharing this row
                unsigned long long key = ((unsigned long long)ford(bmax) << 32)
                                       | (unsigned long long)(0x7FFFFFFFu - (uint32_t)bidx);
                #pragma unroll
                for (int o = 1; o < 4; o <<= 1) {
                    unsigned long long ok = __shfl_xor_sync(0xffffffffu, key, o);
                    if (ok > key) key = ok;
                }
                if ((lane & 3) == 0)
                    skey[mloc * 4 + warp_n] = live ? key : 0ull;
            }
        }
    }
    if (amax) {
        __syncthreads();
        if (tid < 128) {
            int m = m0 + tid;
            if (m < Mv) {
                unsigned long long k0 = skey[tid * 4 + 0];
                unsigned long long k1 = skey[tid * 4 + 1];
                unsigned long long k2 = skey[tid * 4 + 2];
                unsigned long long k3 = skey[tid * 4 + 3];
                unsigned long long k = k0 > k1 ? k0 : k1;
                if (k2 > k) k = k2;
                if (k3 > k) k = k3;
                int t = m >> 6, b = m & 63;
                atomicMax(&amax[b * TS + t], k);
            }
        }
    }
}

// ---------------------------------------------------------------------------
// bf16 hi/lo split kernels
// ---------------------------------------------------------------------------
__global__ void split_k(const float* __restrict__ src, __nv_bfloat16* __restrict__ hi,
                        __nv_bfloat16* __restrict__ lo, size_t n)
{
    size_t i = (size_t)blockIdx.x * blockDim.x + threadIdx.x;
    size_t stride = (size_t)gridDim.x * blockDim.x;
    for (; i < n; i += stride) {
        float v = src[i];
        __nv_bfloat16 h = __float2bfloat16(v);
        hi[i] = h;
        lo[i] = __float2bfloat16(v - __bfloat162float(h));
    }
}
__global__ void split_wih_k(const float* __restrict__ wih, __nv_bfloat16* __restrict__ hi,
                            __nv_bfloat16* __restrict__ lo)
{
    int i = blockIdx.x * blockDim.x + threadIdx.x;
    if (i >= 3 * H_ * H_) return;
    int n = i >> 9, k = i & 511;
    float v = wih[(size_t)n * (H_ + E_) + k];
    __nv_bfloat16 h = __float2bfloat16(v);
    hi[i] = h;
    lo[i] = __float2bfloat16(v - __bfloat162float(h));
}
__global__ void gather_split_k(const float* __restrict__ emb, const int* __restrict__ targets,
                               __nv_bfloat16* __restrict__ hi, __nv_bfloat16* __restrict__ lo)
{
    int idx = blockIdx.x * blockDim.x + threadIdx.x;
    if (idx >= M_PAD * E_) return;
    int r = idx >> 9, e = idx & 511;
    float v = 0.f;
    if (r < M_ALL) {
        int t = r >> 6, b = r & 63;
        v = emb[(size_t)targets[b * T_ + t] * E_ + e];
    }
    __nv_bfloat16 h = __float2bfloat16(v);
    hi[idx] = h;
    lo[idx] = __float2bfloat16(v - __bfloat162float(h));
}
__global__ void zero_pad_hall_k(__nv_bfloat16* __restrict__ hi, __nv_bfloat16* __restrict__ lo)
{
    int i = blockIdx.x * blockDim.x + threadIdx.x;
    int n = (M_PAD - M_ALL) * H_;
    if (i < n) { hi[M_ALL * H_ + i] = __float2bfloat16(0.f); lo[M_ALL * H_ + i] = __float2bfloat16(0.f); }
}
__global__ void init_amax_k(unsigned long long* __restrict__ a)
{
    int i = blockIdx.x * blockDim.x + threadIdx.x;
    if (i < M_ALL) a[i] = 0ull;
}

// ---------------------------------------------------------------------------
// attention collapse (h-independent): wv = W1_enc^T W2^T W3^T v_att
// ---------------------------------------------------------------------------
__global__ void colmatvec_k(const float* __restrict__ Mt, const float* __restrict__ v,
                            float* __restrict__ out, int ldm)
{
    __shared__ float sv[H_];
    int tid = threadIdx.x;
    sv[tid] = v[tid];
    __syncthreads();
    float acc = 0.f;
    #pragma unroll 4
    for (int r = 0; r < H_; r++) acc += sv[r] * Mt[(size_t)r * ldm + tid];
    out[tid] = acc;
}

__global__ void scores_k(const float* __restrict__ enc, const float* __restrict__ wv,
                         float* __restrict__ scores)
{
    int row  = (blockIdx.x * blockDim.x + threadIdx.x) >> 5;
    int lane = threadIdx.x & 31;
    if (row >= B_ * S_) return;
    const float* e = enc + (size_t)row * H_;
    float acc = 0.f;
    #pragma unroll 4
    for (int k = lane; k < H_; k += 32) acc += e[k] * wv[k];
    #pragma unroll
    for (int o = 16; o; o >>= 1) acc += __shfl_xor_sync(0xffffffffu, acc, o);
    if (!lane) scores[row] = acc;
}

__global__ void softctx_k(const float* __restrict__ enc, const float* __restrict__ scores,
                          float* __restrict__ context)
{
    int b = blockIdx.x, tid = threadIdx.x;
    __shared__ float at[S_];
    __shared__ float red[256];
    float sc = (tid < S_) ? scores[b * S_ + tid] : -1e30f;
    red[tid] = sc; __syncthreads();
    for (int s = 128; s; s >>= 1) { if (tid < s) red[tid] = fmaxf(red[tid], red[tid + s]); __syncthreads(); }
    float mx = red[0]; __syncthreads();
    float ex = (tid < S_) ? expf(sc - mx) : 0.f;
    red[tid] = ex; __syncthreads();
    for (int s = 128; s; s >>= 1) { if (tid < s) red[tid] += red[tid + s]; __syncthreads(); }
    float inv = 1.f / red[0];
    if (tid < S_) at[tid] = ex * inv;
    __syncthreads();
    const float* eb = enc + (size_t)b * S_ * H_;
    for (int f = tid; f < H_; f += 256) {
        float acc = 0.f;
        #pragma unroll 8
        for (int s = 0; s < S_; s++) acc += at[s] * eb[(size_t)s * H_ + f];
        context[b * H_ + f] = acc;
    }
}

// ---------------------------------------------------------------------------
// small GEMM: C(64 x N) = A(64 x K) @ B(N x ldb, cols [boff,boff+K))^T + bias
// ---------------------------------------------------------------------------
__global__ void gemm64_k(const float* __restrict__ A, const float* __restrict__ Bm,
                         const float* __restrict__ bias, float* __restrict__ C,
                         int N, int K, int ldb, int boff)
{
    const int BN = 32, BK = 16;
    __shared__ __align__(16) float As[BK][64];
    __shared__ __align__(16) float Bs[BK][BN];
    int tid = threadIdx.x;
    int nblk = blockIdx.x * BN;
    int tx = tid & 7, tg = tid >> 3;
    float acc[2][4] = {};
    for (int k0 = 0; k0 < K; k0 += BK) {
        {
            int m = tid >> 2, kk = (tid & 3) * 4;
            float4 av = *(const float4*)(A + (size_t)m * K + k0 + kk);
            As[kk + 0][m] = av.x; As[kk + 1][m] = av.y;
            As[kk + 2][m] = av.z; As[kk + 3][m] = av.w;
        }
        if (tid < 128) {
            int n = tid >> 2, kk = (tid & 3) * 4;
            float4 bv = *(const float4*)(Bm + (size_t)(nblk + n) * ldb + boff + k0 + kk);
            Bs[kk + 0][n] = bv.x; Bs[kk + 1][n] = bv.y;
            Bs[kk + 2][n] = bv.z; Bs[kk + 3][n] = bv.w;
        }
        __syncthreads();
        #pragma unroll
        for (int kk = 0; kk < BK; kk++) {
            float a0 = As[kk][tg * 2 + 0], a1 = As[kk][tg * 2 + 1];
            float4 bv = *(const float4*)&Bs[kk][tx * 4];
            acc[0][0] += a0 * bv.x; acc[0][1] += a0 * bv.y; acc[0][2] += a0 * bv.z; acc[0][3] += a0 * bv.w;
            acc[1][0] += a1 * bv.x; acc[1][1] += a1 * bv.y; acc[1][2] += a1 * bv.z; acc[1][3] += a1 * bv.w;
        }
        __syncthreads();
    }
    #pragma unroll
    for (int i = 0; i < 2; i++) {
        int m = tg * 2 + i;
        #pragma unroll
        for (int j = 0; j < 4; j++) {
            int n = nblk + tx * 4 + j;
            C[(size_t)m * N + n] = acc[i][j] + (bias ? bias[n] : 0.f);
        }
    }
}

// split-K variant for the recurrence: grid (N/32, 4); y-slice kp covers
// k in [kp*128, kp*128+128); partial written to Cpart + kp*64*N. No bias.
__global__ void gemm64_part_k(const float* __restrict__ A, const float* __restrict__ Bm,
                              float* __restrict__ Cpart, int N)
{
    const int BN = 32, BK = 16, KK = 128;
    __shared__ __align__(16) float As[BK][64];
    __shared__ __align__(16) float Bs[BK][BN];
    int tid = threadIdx.x;
    int nblk = blockIdx.x * BN;
    int kbase = blockIdx.y * KK;
    float* C = Cpart + (size_t)blockIdx.y * 64 * N;
    int tx = tid & 7, tg = tid >> 3;
    float acc[2][4] = {};
    for (int k0 = kbase; k0 < kbase + KK; k0 += BK) {
        {
            int m = tid >> 2, kk = (tid & 3) * 4;
            float4 av = *(const float4*)(A + (size_t)m * H_ + k0 + kk);
            As[kk + 0][m] = av.x; As[kk + 1][m] = av.y;
            As[kk + 2][m] = av.z; As[kk + 3][m] = av.w;
        }
        if (tid < 128) {
            int n = tid >> 2, kk = (tid & 3) * 4;
            float4 bv = *(const float4*)(Bm + (size_t)(nblk + n) * H_ + k0 + kk);
            Bs[kk + 0][n] = bv.x; Bs[kk + 1][n] = bv.y;
            Bs[kk + 2][n] = bv.z; Bs[kk + 3][n] = bv.w;
        }
        __syncthreads();
        #pragma unroll
        for (int kk = 0; kk < BK; kk++) {
            float a0 = As[kk][tg * 2 + 0], a1 = As[kk][tg * 2 + 1];
            float4 bv = *(const float4*)&Bs[kk][tx * 4];
            acc[0][0] += a0 * bv.x; acc[0][1] += a0 * bv.y; acc[0][2] += a0 * bv.z; acc[0][3] += a0 * bv.w;
            acc[1][0] += a1 * bv.x; acc[1][1] += a1 * bv.y; acc[1][2] += a1 * bv.z; acc[1][3] += a1 * bv.w;
        }
        __syncthreads();
    }
    #pragma unroll
    for (int i = 0; i < 2; i++) {
        int m = tg * 2 + i;
        #pragma unroll
        for (int j = 0; j < 4; j++)
            C[(size_t)m * N + nblk + tx * 4 + j] = acc[i][j];
    }
}

__global__ void zero_k(float* __restrict__ p, int n)
{
    int i = blockIdx.x * blockDim.x + threadIdx.x;
    if (i < n) p[i] = 0.f;
}

// GRU gates: sums the 4 split-K gh partials (+b_hh), h_new = (1-z)*n + z*h
__global__ void gates_k(int t, const float* __restrict__ gie, const float* __restrict__ gic,
                        const float* __restrict__ ghp, const float* __restrict__ bhh,
                        float* __restrict__ h,
                        __nv_bfloat16* __restrict__ hallhi, __nv_bfloat16* __restrict__ halllo)
{
    int idx = blockIdx.x * blockDim.x + threadIdx.x;
    if (idx >= B_ * H_) return;
    int b = idx >> 9, k = idx & 511;
    const float* ge = gie + ((size_t)t * B_ + b) * (3 * H_);
    const float* gc = gic + (size_t)b * (3 * H_);
    const size_t row = (size_t)b * (3 * H_);
    const size_t part = (size_t)64 * 3 * H_;
    float g0 = bhh[k], g1 = bhh[H_ + k], g2 = bhh[2 * H_ + k];
    #pragma unroll
    for (int p = 0; p < 4; p++) {
        const float* gp = ghp + p * part + row;
        g0 += gp[k]; g1 += gp[H_ + k]; g2 += gp[2 * H_ + k];
    }
    float r = 1.f / (1.f + expf(-(ge[k]          + gc[k]          + g0)));
    float z = 1.f / (1.f + expf(-(ge[H_ + k]     + gc[H_ + k]     + g1)));
    float n = tanhf(ge[2 * H_ + k] + gc[2 * H_ + k] + r * g2);
    float hn = (1.f - z) * n + z * h[idx];
    h[idx] = hn;
    __nv_bfloat16 hh = __float2bfloat16(hn);
    size_t o = ((size_t)t * B_ + b) * H_ + k;
    hallhi[o] = hh;
    halllo[o] = __float2bfloat16(hn - __bfloat162float(hh));
}

__global__ void preds_k(const unsigned long long* __restrict__ amax, float* __restrict__ preds)
{
    int q = blockIdx.x * blockDim.x + threadIdx.x;
    if (q < M_ALL)
        preds[q] = (float)(0x7FFFFFFFu - (uint32_t)(amax[q] & 0xFFFFFFFFull));
}

// ---------------------------------------------------------------------------
extern "C" void kernel_launch(void* const* d_in, const int* in_sizes, int n_in,
                              void* d_out, int out_size)
{
    const float* enc     = (const float*)d_in[0];
    const int*   targets = (const int*)  d_in[1];
    const float* emb     = (const float*)d_in[2];
    const float* W1      = (const float*)d_in[3];
    const float* W2      = (const float*)d_in[5];
    const float* W3      = (const float*)d_in[7];
    const float* v_att   = (const float*)d_in[9];
    const float* W_ih    = (const float*)d_in[10];
    const float* b_ih    = (const float*)d_in[11];
    const float* W_hh    = (const float*)d_in[12];
    const float* b_hh    = (const float*)d_in[13];
    const float* W_out   = (const float*)d_in[14];
    const float* b_out   = (const float*)d_in[15];
    float* out = (float*)d_out;

    Scratch* s;
    cudaGetSymbolAddress((void**)&s, g_s);
    cudaFuncSetAttribute(gemm_mma_k, cudaFuncAttributeMaxDynamicSharedMemorySize, MMA_SMEM);

    const bool want_preds = out_size >= (int)((size_t)M_ALL * V_ + M_ALL);

    // ---- splits / gathers (launches 0-4) ----
    gather_split_k<<<(M_PAD * E_ + 255) / 256, 256>>>(emb, targets, s->emb_hi, s->emb_lo);
    split_wih_k<<<(3 * H_ * H_ + 255) / 256, 256>>>(W_ih, s->wih_hi, s->wih_lo);
    zero_pad_hall_k<<<((M_PAD - M_ALL) * H_ + 255) / 256, 256>>>(s->hall_hi, s->hall_lo);
    split_k<<<4096, 256>>>(W_out, s->wout_hi, s->wout_lo, (size_t)V_ * H_);
    init_amax_k<<<(M_ALL + 255) / 256, 256>>>(s->amax);

    // gie (1856 x 1536) = embA @ W_ih[:, :512]^T — launch #5 (ncu-profiled)
    {
        dim3 grid(3 * H_ / 128, M_PAD / 128);
        gemm_mma_k<<<grid, 256, MMA_SMEM>>>(s->emb_hi, s->emb_lo, s->wih_hi, s->wih_lo,
                                            nullptr, s->gie, 3 * H_, M_ALL, 0, nullptr);
    }

    // ---- attention is h-independent: collapse it entirely ----
    colmatvec_k<<<1, 512>>>(W3, v_att, s->w3v, H_);
    colmatvec_k<<<1, 512>>>(W2, s->w3v, s->w2v, H_);
    colmatvec_k<<<1, 512>>>(W1, s->w2v, s->wv, 2 * H_);
    scores_k<<<(B_ * S_ * 32 + 255) / 256, 256>>>(enc, s->wv, s->scores);
    softctx_k<<<B_, 256>>>(enc, s->scores, s->context);

    // gic = context @ W_ih[:,512:]^T + b_ih   (64 x 1536)
    gemm64_k<<<3 * H_ / 32, 256>>>(s->context, W_ih, b_ih, s->gic, 3 * H_, H_, H_ + E_, E_);

    // ---- sequential GRU recurrence (split-K x4 GEMM + fused-sum gates) ----
    zero_k<<<(B_ * H_ + 255) / 256, 256>>>(s->h, B_ * H_);
    for (int t = 0; t < TS; t++) {
        dim3 g(3 * H_ / 32, 4);
        gemm64_part_k<<<g, 256>>>(s->h, W_hh, s->gh_part, 3 * H_);
        gates_k<<<(B_ * H_ + 255) / 256, 256>>>(t, s->gie, s->gic, s->gh_part, b_hh,
                                                s->h, s->hall_hi, s->hall_lo);
    }

    // ---- logits (1856 x 32000) + fused argmax ----
    {
        dim3 grid(V_ / 128, M_PAD / 128);
        gemm_mma_k<<<grid, 256, MMA_SMEM>>>(s->hall_hi, s->hall_lo, s->wout_hi, s->wout_lo,
                                            b_out, out, V_, M_ALL, 1,
                                            want_preds ? s->amax : nullptr);
    }
    if (want_preds)
        preds_k<<<(M_ALL + 255) / 256, 256>>>(s->amax, out + (size_t)M_ALL * V_);
}

// round 8
// speedup vs baseline: 2.3509x; 1.0499x over previous
#include <cuda_runtime.h>
#include <cuda_bf16.h>
#include <math.h>
#include <stdint.h>

#define B_    64
#define S_    80
#define H_    512
#define E_    512
#define T_    30
#define V_    32000
#define TS    29           // decode steps = T-1
#define M_ALL (TS * B_)    // 1856
#define M_PAD 1920         // 15 * 128 (= 30 * 64)

// ---------------------------------------------------------------------------
// Scratch (static __device__ memory; no allocations anywhere)
// ---------------------------------------------------------------------------
struct Scratch {
    float w3v[H_];
    float w2v[H_];
    float wv[H_];
    float scores[B_ * S_];
    float context[B_ * H_];
    float gic[B_ * 3 * H_];
    float gh_part[4 * B_ * 3 * H_];          // split-K partials of h @ W_hh^T
    float h[B_ * H_];
    float gie[M_ALL * 3 * H_];               // embedding half of gi, all steps
    unsigned long long amax[M_ALL];          // fused argmax keys
    __nv_bfloat16 emb_hi[M_PAD * E_];        // gathered embeddings, bf16 split
    __nv_bfloat16 emb_lo[M_PAD * E_];
    __nv_bfloat16 hall_hi[M_PAD * H_];       // h_new all steps, bf16 split
    __nv_bfloat16 hall_lo[M_PAD * H_];
    __nv_bfloat16 wih_hi[3 * H_ * H_];       // W_ih[:, :512] split
    __nv_bfloat16 wih_lo[3 * H_ * H_];
    __nv_bfloat16 wout_hi[(size_t)V_ * H_];  // W_out split
    __nv_bfloat16 wout_lo[(size_t)V_ * H_];
};
__device__ Scratch g_s;

__device__ __forceinline__ uint32_t smem_u32(const void* p) {
    uint32_t a;
    asm("{ .reg .u64 t; cvta.to.shared.u64 t, %1; cvt.u32.u64 %0, t; }" : "=r"(a) : "l"(p));
    return a;
}
__device__ __forceinline__ void cp_async16(uint32_t dst, const void* src) {
    asm volatile("cp.async.cg.shared.global [%0], [%1], 16;" :: "r"(dst), "l"(src));
}
__device__ __forceinline__ void ldsm_x4(uint32_t* r, uint32_t addr) {
    asm volatile("ldmatrix.sync.aligned.m8n8.x4.shared.b16 {%0,%1,%2,%3}, [%4];"
                 : "=r"(r[0]), "=r"(r[1]), "=r"(r[2]), "=r"(r[3]) : "r"(addr));
}
__device__ __forceinline__ void mma_bf16(float* d, const uint32_t* a, const uint32_t* b) {
    asm volatile("mma.sync.aligned.m16n8k16.row.col.f32.bf16.bf16.f32 "
                 "{%0,%1,%2,%3}, {%4,%5,%6,%7}, {%8,%9}, {%0,%1,%2,%3};"
                 : "+f"(d[0]), "+f"(d[1]), "+f"(d[2]), "+f"(d[3])
                 : "r"(a[0]), "r"(a[1]), "r"(a[2]), "r"(a[3]), "r"(b[0]), "r"(b[1]));
}
// monotonic float -> uint order map
__device__ __forceinline__ uint32_t ford(float f) {
    uint32_t u = __float_as_uint(f);
    return u ^ ((uint32_t)((int32_t)u >> 31) | 0x80000000u);
}
__device__ __forceinline__ uint32_t pack_bf2(float a, float b) {
    __nv_bfloat162 p = __halves2bfloat162(__float2bfloat16(a), __float2bfloat16(b));
    return *(uint32_t*)&p;
}

// ===========================================================================
// mma.sync GEMM: C(M x N) = A(M x 512) @ B(N x 512)^T + bias, bf16 split:
//   C = Ahi*Bhi + Ahi*Blo + Alo*Bhi   (fp32 accumulate)
// CTA tile 64x128, 256 threads (8 warps = 2x4, warp tile 32x32), K chunks 64,
// cp.async 2-stage pipeline, 96 KB smem -> 2 CTAs/SM, SW128 swizzle, ldmatrix.
// mode 0: row-major C.  mode 1: row m=t*64+b -> C[(b*TS+t)*N + n]
// amax (optional): per-global-row argmax keys merged via atomicMax.
// ===========================================================================
#define STG_BYTES 49152          // one stage: Ah 8K | Al 8K | Bh 16K | Bl 16K
#define MMA_SMEM  (2 * STG_BYTES)

__global__ void __launch_bounds__(256, 2) gemm_mma_k(
    const __nv_bfloat16* __restrict__ Ahi, const __nv_bfloat16* __restrict__ Alo,
    const __nv_bfloat16* __restrict__ Bhi, const __nv_bfloat16* __restrict__ Blo,
    const float* __restrict__ bias, float* __restrict__ C,
    int N, int Mv, int mode, unsigned long long* __restrict__ amax)
{
    extern __shared__ __align__(1024) char dsm[];
    const uint32_t sbase = smem_u32(dsm);
    const int tid = threadIdx.x, lane = tid & 31, wid = tid >> 5;
    const int warp_m = wid >> 2, warp_n = wid & 3;      // 2 x 4 warp grid
    const int m0 = blockIdx.y * 64, n0 = blockIdx.x * 128;

    float acc[2][4][4];
    #pragma unroll
    for (int i = 0; i < 2; i++)
        #pragma unroll
        for (int j = 0; j < 4; j++)
            #pragma unroll
            for (int r = 0; r < 4; r++) acc[i][j][r] = 0.f;

    // ---- stage loader: A 64 rows, B 128 rows, 64 bf16/row, SW128 swizzle ----
    auto issue = [&](int c) {
        const uint32_t stg = sbase + (c & 1) * STG_BYTES;
        const int kc = c * 64;
        #pragma unroll
        for (int i = 0; i < 2; i++) {                    // A hi/lo: 512 each
            int q = i * 256 + tid;
            int row = q >> 3, u = q & 7;
            uint32_t off = row * 128 + (((uint32_t)u ^ (uint32_t)(row & 7)) << 4);
            cp_async16(stg + off,        Ahi + (size_t)(m0 + row) * 512 + kc + u * 8);
            cp_async16(stg + 8192 + off, Alo + (size_t)(m0 + row) * 512 + kc + u * 8);
        }
        #pragma unroll
        for (int i = 0; i < 4; i++) {                    // B hi/lo: 1024 each
            int q = i * 256 + tid;
            int row = q >> 3, u = q & 7;
            uint32_t off = row * 128 + (((uint32_t)u ^ (uint32_t)(row & 7)) << 4);
            cp_async16(stg + 16384 + off, Bhi + (size_t)(n0 + row) * 512 + kc + u * 8);
            cp_async16(stg + 32768 + off, Blo + (size_t)(n0 + row) * 512 + kc + u * 8);
        }
    };

    issue(0);
    asm volatile("cp.async.commit_group;" ::: "memory");

    for (int c = 0; c < 8; c++) {
        if (c + 1 < 8) {
            issue(c + 1);
            asm volatile("cp.async.commit_group;" ::: "memory");
            asm volatile("cp.async.wait_group 1;" ::: "memory");
        } else {
            asm volatile("cp.async.wait_group 0;" ::: "memory");
        }
        __syncthreads();

        const uint32_t stg = sbase + (c & 1) * STG_BYTES;
        #pragma unroll
        for (int ks = 0; ks < 4; ks++) {
            uint32_t ah[2][4], al[2][4];
            #pragma unroll
            for (int mi = 0; mi < 2; mi++) {
                int row = warp_m * 32 + mi * 16 + (lane & 15);
                uint32_t unit = ((uint32_t)(ks * 2 + (lane >> 4))) ^ (uint32_t)(row & 7);
                uint32_t a = stg + row * 128 + unit * 16;
                ldsm_x4(ah[mi], a);
                ldsm_x4(al[mi], a + 8192);
            }
            uint32_t bh[4][2], bl[4][2];
            #pragma unroll
            for (int p = 0; p < 2; p++) {
                int g = lane >> 3;
                int row = warp_n * 32 + (2 * p + (g >> 1)) * 8 + (lane & 7);
                uint32_t unit = ((uint32_t)(ks * 2 + (g & 1))) ^ (uint32_t)(row & 7);
                uint32_t a = stg + 16384 + row * 128 + unit * 16;
                uint32_t rh[4], rl[4];
                ldsm_x4(rh, a);
                ldsm_x4(rl, a + 16384);
                bh[2*p][0] = rh[0]; bh[2*p][1] = rh[1]; bh[2*p+1][0] = rh[2]; bh[2*p+1][1] = rh[3];
                bl[2*p][0] = rl[0]; bl[2*p][1] = rl[1]; bl[2*p+1][0] = rl[2]; bl[2*p+1][1] = rl[3];
            }
            #pragma unroll
            for (int mi = 0; mi < 2; mi++)
                #pragma unroll
                for (int ni = 0; ni < 4; ni++) {
                    mma_bf16(acc[mi][ni], ah[mi], bh[ni]);
                    mma_bf16(acc[mi][ni], ah[mi], bl[ni]);
                    mma_bf16(acc[mi][ni], al[mi], bh[ni]);
                }
        }
        __syncthreads();
    }

    // ---- epilogue (+ optional fused per-row argmax) ----
    unsigned long long* skey = (unsigned long long*)dsm;   // reuse smem: [64][4]
    #pragma unroll
    for (int mi = 0; mi < 2; mi++) {
        #pragma unroll
        for (int half = 0; half < 2; half++) {
            int mloc = warp_m * 32 + mi * 16 + (lane >> 2) + half * 8;
            int m = m0 + mloc;
            bool live = (m < Mv);
            float* crow = C;
            if (live) {
                if (mode == 0) crow = C + (size_t)m * N;
                else { int t = m >> 6, b = m & 63; crow = C + ((size_t)b * TS + t) * N; }
            }
            float bmax = -3.4e38f; int bidx = 0;
            #pragma unroll
            for (int ni = 0; ni < 4; ni++) {
                int n = n0 + warp_n * 32 + ni * 8 + (lane & 3) * 2;
                float v0 = acc[mi][ni][half * 2 + 0];
                float v1 = acc[mi][ni][half * 2 + 1];
                if (bias) { v0 += bias[n]; v1 += bias[n + 1]; }
                if (live) {
                    *(float2*)&crow[n] = make_float2(v0, v1);
                    if (amax) {
                        if (v0 > bmax) { bmax = v0; bidx = n; }
                        if (v1 > bmax) { bmax = v1; bidx = n + 1; }
                    }
                }
            }
            if (amax) {
                unsigned long long key = ((unsigned long long)ford(bmax) << 32)
                                       | (unsigned long long)(0x7FFFFFFFu - (uint32_t)bidx);
                #pragma unroll
                for (int o = 1; o < 4; o <<= 1) {
                    unsigned long long ok = __shfl_xor_sync(0xffffffffu, key, o);
                    if (ok > key) key = ok;
                }
                if ((lane & 3) == 0)
                    skey[mloc * 4 + warp_n] = live ? key : 0ull;
            }
        }
    }
    if (amax) {
        __syncthreads();
        if (tid < 64) {
            int m = m0 + tid;
            if (m < Mv) {
                unsigned long long k0 = skey[tid * 4 + 0];
                unsigned long long k1 = skey[tid * 4 + 1];
                unsigned long long k2 = skey[tid * 4 + 2];
                unsigned long long k3 = skey[tid * 4 + 3];
                unsigned long long k = k0 > k1 ? k0 : k1;
                if (k2 > k) k = k2;
                if (k3 > k) k = k3;
                int t = m >> 6, b = m & 63;
                atomicMax(&amax[b * TS + t], k);
            }
        }
    }
}

// ---------------------------------------------------------------------------
// vectorized bf16 hi/lo split kernels (float4 in, packed uint2 out)
// ---------------------------------------------------------------------------
__global__ void split_k(const float4* __restrict__ src, uint2* __restrict__ hi,
                        uint2* __restrict__ lo, int n4)
{
    int i = blockIdx.x * blockDim.x + threadIdx.x;
    int stride = gridDim.x * blockDim.x;
    for (; i < n4; i += stride) {
        float4 v = src[i];
        uint2 hp, lp;
        hp.x = pack_bf2(v.x, v.y); hp.y = pack_bf2(v.z, v.w);
        __nv_bfloat162 h0 = *(__nv_bfloat162*)&hp.x;
        __nv_bfloat162 h1 = *(__nv_bfloat162*)&hp.y;
        lp.x = pack_bf2(v.x - __bfloat162float(h0.x), v.y - __bfloat162float(h0.y));
        lp.y = pack_bf2(v.z - __bfloat162float(h1.x), v.w - __bfloat162float(h1.y));
        hi[i] = hp; lo[i] = lp;
    }
}
// split first 512 cols of W_ih (row stride 1024 floats)
__global__ void split_wih_k(const float* __restrict__ wih, uint2* __restrict__ hi,
                            uint2* __restrict__ lo)
{
    int i = blockIdx.x * blockDim.x + threadIdx.x;     // over groups of 4
    if (i >= 3 * H_ * H_ / 4) return;
    int n = i >> 7, k4 = i & 127;
    float4 v = *(const float4*)(wih + (size_t)n * (H_ + E_) + k4 * 4);
    uint2 hp, lp;
    hp.x = pack_bf2(v.x, v.y); hp.y = pack_bf2(v.z, v.w);
    __nv_bfloat162 h0 = *(__nv_bfloat162*)&hp.x;
    __nv_bfloat162 h1 = *(__nv_bfloat162*)&hp.y;
    lp.x = pack_bf2(v.x - __bfloat162float(h0.x), v.y - __bfloat162float(h0.y));
    lp.y = pack_bf2(v.z - __bfloat162float(h1.x), v.w - __bfloat162float(h1.y));
    hi[i] = hp; lo[i] = lp;
}
// gather target embeddings into split form; rows >= M_ALL zero-padded
__global__ void gather_split_k(const float* __restrict__ emb, const int* __restrict__ targets,
                               uint2* __restrict__ hi, uint2* __restrict__ lo)
{
    int i = blockIdx.x * blockDim.x + threadIdx.x;     // over groups of 4
    if (i >= M_PAD * E_ / 4) return;
    int r = i >> 7, e4 = i & 127;
    uint2 hp = make_uint2(0u, 0u), lp = make_uint2(0u, 0u);
    if (r < M_ALL) {
        int t = r >> 6, b = r & 63;
        float4 v = *(const float4*)(emb + (size_t)targets[b * T_ + t] * E_ + e4 * 4);
        hp.x = pack_bf2(v.x, v.y); hp.y = pack_bf2(v.z, v.w);
        __nv_bfloat162 h0 = *(__nv_bfloat162*)&hp.x;
        __nv_bfloat162 h1 = *(__nv_bfloat162*)&hp.y;
        lp.x = pack_bf2(v.x - __bfloat162float(h0.x), v.y - __bfloat162float(h0.y));
        lp.y = pack_bf2(v.z - __bfloat162float(h1.x), v.w - __bfloat162float(h1.y));
    }
    hi[i] = hp; lo[i] = lp;
}
// zero-pad hall tail + init amax keys (fused misc init)
__global__ void misc_init_k(uint32_t* __restrict__ hi, uint32_t* __restrict__ lo,
                            unsigned long long* __restrict__ a)
{
    int i = blockIdx.x * blockDim.x + threadIdx.x;
    const int npad = (M_PAD - M_ALL) * H_ / 2;         // 16384 uint32 each
    if (i < npad) {
        hi[M_ALL * H_ / 2 + i] = 0u;
        lo[M_ALL * H_ / 2 + i] = 0u;
    }
    if (i < M_ALL) a[i] = 0ull;
}

// ---------------------------------------------------------------------------
// attention collapse (h-independent): wv = W1_enc^T W2^T W3^T v_att
// ---------------------------------------------------------------------------
__global__ void colmatvec_k(const float* __restrict__ Mt, const float* __restrict__ v,
                            float* __restrict__ out, int ldm)
{
    __shared__ float sv[H_];
    int tid = threadIdx.x;
    sv[tid] = v[tid];
    __syncthreads();
    float acc = 0.f;
    #pragma unroll 4
    for (int r = 0; r < H_; r++) acc += sv[r] * Mt[(size_t)r * ldm + tid];
    out[tid] = acc;
}

__global__ void scores_k(const float* __restrict__ enc, const float* __restrict__ wv,
                         float* __restrict__ scores)
{
    int row  = (blockIdx.x * blockDim.x + threadIdx.x) >> 5;
    int lane = threadIdx.x & 31;
    if (row >= B_ * S_) return;
    const float* e = enc + (size_t)row * H_;
    float acc = 0.f;
    #pragma unroll 4
    for (int k = lane; k < H_; k += 32) acc += e[k] * wv[k];
    #pragma unroll
    for (int o = 16; o; o >>= 1) acc += __shfl_xor_sync(0xffffffffu, acc, o);
    if (!lane) scores[row] = acc;
}

__global__ void softctx_k(const float* __restrict__ enc, const float* __restrict__ scores,
                          float* __restrict__ context)
{
    int b = blockIdx.x, tid = threadIdx.x;
    __shared__ float at[S_];
    __shared__ float red[256];
    float sc = (tid < S_) ? scores[b * S_ + tid] : -1e30f;
    red[tid] = sc; __syncthreads();
    for (int s = 128; s; s >>= 1) { if (tid < s) red[tid] = fmaxf(red[tid], red[tid + s]); __syncthreads(); }
    float mx = red[0]; __syncthreads();
    float ex = (tid < S_) ? expf(sc - mx) : 0.f;
    red[tid] = ex; __syncthreads();
    for (int s = 128; s; s >>= 1) { if (tid < s) red[tid] += red[tid + s]; __syncthreads(); }
    float inv = 1.f / red[0];
    if (tid < S_) at[tid] = ex * inv;
    __syncthreads();
    const float* eb = enc + (size_t)b * S_ * H_;
    for (int f = tid; f < H_; f += 256) {
        float acc = 0.f;
        #pragma unroll 8
        for (int s = 0; s < S_; s++) acc += at[s] * eb[(size_t)s * H_ + f];
        context[b * H_ + f] = acc;
    }
}

// ---------------------------------------------------------------------------
// small GEMM: C(64 x N) = A(64 x K) @ B(N x ldb, cols [boff,boff+K))^T + bias
// ---------------------------------------------------------------------------
__global__ void gemm64_k(const float* __restrict__ A, const float* __restrict__ Bm,
                         const float* __restrict__ bias, float* __restrict__ C,
                         int N, int K, int ldb, int boff)
{
    const int BN = 32, BK = 16;
    __shared__ __align__(16) float As[BK][64];
    __shared__ __align__(16) float Bs[BK][BN];
    int tid = threadIdx.x;
    int nblk = blockIdx.x * BN;
    int tx = tid & 7, tg = tid >> 3;
    float acc[2][4] = {};
    for (int k0 = 0; k0 < K; k0 += BK) {
        {
            int m = tid >> 2, kk = (tid & 3) * 4;
            float4 av = *(const float4*)(A + (size_t)m * K + k0 + kk);
            As[kk + 0][m] = av.x; As[kk + 1][m] = av.y;
            As[kk + 2][m] = av.z; As[kk + 3][m] = av.w;
        }
        if (tid < 128) {
            int n = tid >> 2, kk = (tid & 3) * 4;
            float4 bv = *(const float4*)(Bm + (size_t)(nblk + n) * ldb + boff + k0 + kk);
            Bs[kk + 0][n] = bv.x; Bs[kk + 1][n] = bv.y;
            Bs[kk + 2][n] = bv.z; Bs[kk + 3][n] = bv.w;
        }
        __syncthreads();
        #pragma unroll
        for (int kk = 0; kk < BK; kk++) {
            float a0 = As[kk][tg * 2 + 0], a1 = As[kk][tg * 2 + 1];
            float4 bv = *(const float4*)&Bs[kk][tx * 4];
            acc[0][0] += a0 * bv.x; acc[0][1] += a0 * bv.y; acc[0][2] += a0 * bv.z; acc[0][3] += a0 * bv.w;
            acc[1][0] += a1 * bv.x; acc[1][1] += a1 * bv.y; acc[1][2] += a1 * bv.z; acc[1][3] += a1 * bv.w;
        }
        __syncthreads();
    }
    #pragma unroll
    for (int i = 0; i < 2; i++) {
        int m = tg * 2 + i;
        #pragma unroll
        for (int j = 0; j < 4; j++) {
            int n = nblk + tx * 4 + j;
            C[(size_t)m * N + n] = acc[i][j] + (bias ? bias[n] : 0.f);
        }
    }
}

// split-K variant for the recurrence: grid (N/32, 4); y-slice kp covers
// k in [kp*128, kp*128+128); partial written to Cpart + kp*64*N. No bias.
__global__ void gemm64_part_k(const float* __restrict__ A, const float* __restrict__ Bm,
                              float* __restrict__ Cpart, int N)
{
    const int BN = 32, BK = 16, KK = 128;
    __shared__ __align__(16) float As[BK][64];
    __shared__ __align__(16) float Bs[BK][BN];
    int tid = threadIdx.x;
    int nblk = blockIdx.x * BN;
    int kbase = blockIdx.y * KK;
    float* C = Cpart + (size_t)blockIdx.y * 64 * N;
    int tx = tid & 7, tg = tid >> 3;
    float acc[2][4] = {};
    for (int k0 = kbase; k0 < kbase + KK; k0 += BK) {
        {
            int m = tid >> 2, kk = (tid & 3) * 4;
            float4 av = *(const float4*)(A + (size_t)m * H_ + k0 + kk);
            As[kk + 0][m] = av.x; As[kk + 1][m] = av.y;
            As[kk + 2][m] = av.z; As[kk + 3][m] = av.w;
        }
        if (tid < 128) {
            int n = tid >> 2, kk = (tid & 3) * 4;
            float4 bv = *(const float4*)(Bm + (size_t)(nblk + n) * H_ + k0 + kk);
            Bs[kk + 0][n] = bv.x; Bs[kk + 1][n] = bv.y;
            Bs[kk + 2][n] = bv.z; Bs[kk + 3][n] = bv.w;
        }
        __syncthreads();
        #pragma unroll
        for (int kk = 0; kk < BK; kk++) {
            float a0 = As[kk][tg * 2 + 0], a1 = As[kk][tg * 2 + 1];
            float4 bv = *(const float4*)&Bs[kk][tx * 4];
            acc[0][0] += a0 * bv.x; acc[0][1] += a0 * bv.y; acc[0][2] += a0 * bv.z; acc[0][3] += a0 * bv.w;
            acc[1][0] += a1 * bv.x; acc[1][1] += a1 * bv.y; acc[1][2] += a1 * bv.z; acc[1][3] += a1 * bv.w;
        }
        __syncthreads();
    }
    #pragma unroll
    for (int i = 0; i < 2; i++) {
        int m = tg * 2 + i;
        #pragma unroll
        for (int j = 0; j < 4; j++)
            C[(size_t)m * N + nblk + tx * 4 + j] = acc[i][j];
    }
}

__global__ void zero_k(float* __restrict__ p, int n)
{
    int i = blockIdx.x * blockDim.x + threadIdx.x;
    if (i < n) p[i] = 0.f;
}

// GRU gates: sums the 4 split-K gh partials (+b_hh), h_new = (1-z)*n + z*h
__global__ void gates_k(int t, const float* __restrict__ gie, const float* __restrict__ gic,
                        const float* __restrict__ ghp, const float* __restrict__ bhh,
                        float* __restrict__ h,
                        __nv_bfloat16* __restrict__ hallhi, __nv_bfloat16* __restrict__ halllo)
{
    int idx = blockIdx.x * blockDim.x + threadIdx.x;
    if (idx >= B_ * H_) return;
    int b = idx >> 9, k = idx & 511;
    const float* ge = gie + ((size_t)t * B_ + b) * (3 * H_);
    const float* gc = gic + (size_t)b * (3 * H_);
    const size_t row = (size_t)b * (3 * H_);
    const size_t part = (size_t)64 * 3 * H_;
    float g0 = bhh[k], g1 = bhh[H_ + k], g2 = bhh[2 * H_ + k];
    #pragma unroll
    for (int p = 0; p < 4; p++) {
        const float* gp = ghp + p * part + row;
        g0 += gp[k]; g1 += gp[H_ + k]; g2 += gp[2 * H_ + k];
    }
    float r = 1.f / (1.f + expf(-(ge[k]          + gc[k]          + g0)));
    float z = 1.f / (1.f + expf(-(ge[H_ + k]     + gc[H_ + k]     + g1)));
    float n = tanhf(ge[2 * H_ + k] + gc[2 * H_ + k] + r * g2);
    float hn = (1.f - z) * n + z * h[idx];
    h[idx] = hn;
    __nv_bfloat16 hh = __float2bfloat16(hn);
    size_t o = ((size_t)t * B_ + b) * H_ + k;
    hallhi[o] = hh;
    halllo[o] = __float2bfloat16(hn - __bfloat162float(hh));
}

__global__ void preds_k(const unsigned long long* __restrict__ amax, float* __restrict__ preds)
{
    int q = blockIdx.x * blockDim.x + threadIdx.x;
    if (q < M_ALL)
        preds[q] = (float)(0x7FFFFFFFu - (uint32_t)(amax[q] & 0xFFFFFFFFull));
}

// ---------------------------------------------------------------------------
extern "C" void kernel_launch(void* const* d_in, const int* in_sizes, int n_in,
                              void* d_out, int out_size)
{
    const float* enc     = (const float*)d_in[0];
    const int*   targets = (const int*)  d_in[1];
    const float* emb     = (const float*)d_in[2];
    const float* W1      = (const float*)d_in[3];
    const float* W2      = (const float*)d_in[5];
    const float* W3      = (const float*)d_in[7];
    const float* v_att   = (const float*)d_in[9];
    const float* W_ih    = (const float*)d_in[10];
    const float* b_ih    = (const float*)d_in[11];
    const float* W_hh    = (const float*)d_in[12];
    const float* b_hh    = (const float*)d_in[13];
    const float* W_out   = (const float*)d_in[14];
    const float* b_out   = (const float*)d_in[15];
    float* out = (float*)d_out;

    Scratch* s;
    cudaGetSymbolAddress((void**)&s, g_s);
    cudaFuncSetAttribute(gemm_mma_k, cudaFuncAttributeMaxDynamicSharedMemorySize, MMA_SMEM);

    const bool want_preds = out_size >= (int)((size_t)M_ALL * V_ + M_ALL);

    // ---- launches 1-3: gathers / inits ----
    gather_split_k<<<(M_PAD * E_ / 4 + 255) / 256, 256>>>(emb, targets,
                                                          (uint2*)s->emb_hi, (uint2*)s->emb_lo);
    split_wih_k<<<(3 * H_ * H_ / 4 + 255) / 256, 256>>>(W_ih, (uint2*)s->wih_hi, (uint2*)s->wih_lo);
    misc_init_k<<<64, 256>>>((uint32_t*)s->hall_hi, (uint32_t*)s->hall_lo, s->amax);

    // ---- launch 4 (ncu-profiled): gie (1856 x 1536) = embA @ W_ih[:, :512]^T ----
    {
        dim3 grid(3 * H_ / 128, M_PAD / 64);
        gemm_mma_k<<<grid, 256, MMA_SMEM>>>(s->emb_hi, s->emb_lo, s->wih_hi, s->wih_lo,
                                            nullptr, s->gie, 3 * H_, M_ALL, 0, nullptr);
    }

    // ---- W_out split (before logits) ----
    split_k<<<2048, 256>>>((const float4*)W_out, (uint2*)s->wout_hi, (uint2*)s->wout_lo,
                           (int)((size_t)V_ * H_ / 4));

    // ---- attention is h-independent: collapse it entirely ----
    colmatvec_k<<<1, 512>>>(W3, v_att, s->w3v, H_);
    colmatvec_k<<<1, 512>>>(W2, s->w3v, s->w2v, H_);
    colmatvec_k<<<1, 512>>>(W1, s->w2v, s->wv, 2 * H_);
    scores_k<<<(B_ * S_ * 32 + 255) / 256, 256>>>(enc, s->wv, s->scores);
    softctx_k<<<B_, 256>>>(enc, s->scores, s->context);

    // gic = context @ W_ih[:,512:]^T + b_ih   (64 x 1536)
    gemm64_k<<<3 * H_ / 32, 256>>>(s->context, W_ih, b_ih, s->gic, 3 * H_, H_, H_ + E_, E_);

    // ---- sequential GRU recurrence (split-K x4 GEMM + fused-sum gates) ----
    zero_k<<<(B_ * H_ + 255) / 256, 256>>>(s->h, B_ * H_);
    for (int t = 0; t < TS; t++) {
        dim3 g(3 * H_ / 32, 4);
        gemm64_part_k<<<g, 256>>>(s->h, W_hh, s->gh_part, 3 * H_);
        gates_k<<<(B_ * H_ + 255) / 256, 256>>>(t, s->gie, s->gic, s->gh_part, b_hh,
                                                s->h, s->hall_hi, s->hall_lo);
    }

    // ---- logits (1856 x 32000) + fused argmax ----
    {
        dim3 grid(V_ / 128, M_PAD / 64);
        gemm_mma_k<<<grid, 256, MMA_SMEM>>>(s->hall_hi, s->hall_lo, s->wout_hi, s->wout_lo,
                                            b_out, out, V_, M_ALL, 1,
                                            want_preds ? s->amax : nullptr);
    }
    if (want_preds)
        preds_k<<<(M_ALL + 255) / 256, 256>>>(s->amax, out + (size_t)M_ALL * V_);
}